// round 5
// baseline (speedup 1.0000x reference)
#include <cuda_runtime.h>
#include <cstdint>

#define NSP     2048
#define BATCH   64
#define NSTEP   1000
#define KEX     32          // steps between ghost exchanges
#define GW      64          // ghost elems per side (= 2*KEX) = 16 groups
#define OWNW    128         // owned elems per warp
#define NG      2           // float4 groups per thread
#define THREADS 256         // 8 warps
#define OWN_CTA 1024        // owned per CTA (half row)

typedef unsigned long long u64;

__device__ __forceinline__ u64 pk(float lo, float hi) {
    u64 r; asm("mov.b64 %0,{%1,%2};" : "=l"(r) : "f"(lo), "f"(hi)); return r;
}
__device__ __forceinline__ void upk(u64 v, float& lo, float& hi) {
    asm("mov.b64 {%0,%1},%2;" : "=f"(lo), "=f"(hi) : "l"(v));
}
__device__ __forceinline__ u64 fma2(u64 a, u64 b, u64 c) {
    u64 d; asm("fma.rn.f32x2 %0,%1,%2,%3;" : "=l"(d) : "l"(a), "l"(b), "l"(c)); return d;
}
__device__ __forceinline__ u64 add2(u64 a, u64 b) {
    u64 d; asm("add.rn.f32x2 %0,%1,%2;" : "=l"(d) : "l"(a), "l"(b)); return d;
}
__device__ __forceinline__ u64 mul2(u64 a, u64 b) {
    u64 d; asm("mul.rn.f32x2 %0,%1,%2;" : "=l"(d) : "l"(a), "l"(b)); return d;
}

__global__ void __cluster_dims__(2, 1, 1) __launch_bounds__(THREADS, 1)
ks_kernel(const float* __restrict__ u0,
          const float* __restrict__ cp,
          const float* __restrict__ ap,
          const float* __restrict__ bp,
          float* __restrict__ out) {
    __shared__ alignas(16) float sh[OWN_CTA];   // exchange staging (4 KB)

    const int row  = blockIdx.x >> 1;
    const int half = blockIdx.x & 1;
    const int w    = threadIdx.x >> 5;
    const int lane = threadIdx.x & 31;
    const unsigned FULL = 0xffffffffu;

    const float dt = 0.01f;
    const float Af = -0.5f * dt * (*cp);
    const float Bc = -dt * (*ap);
    const float Cc = -dt * (*bp);
    const float c0f = 1.0f - 2.0f * Bc + 6.0f * Cc;
    const float c1f = Bc - 4.0f * Cc;
    const u64 C0 = pk(c0f, c0f), C1 = pk(c1f, c1f), C2 = pk(Cc, Cc);
    const u64 AV = pk(Af, Af),   M1 = pk(-1.0f, -1.0f);

    // warp cover start (global row coordinate of local elem 0; may be negative)
    const int ws = half * OWN_CTA + w * OWNW - GW;

    // interleaved groups: group m = g*32+lane covers elems [ws+4m, ws+4m+4)
    // owned groups: m in [16,48)  ->  g==0: lane>=16 ; g==1: lane<16
    u64 Plo[NG], Phi[NG];

    const float* urow = u0 + (size_t)row * NSP;
    #pragma unroll
    for (int g = 0; g < NG; g++) {
        int pos = (ws + 4 * (g * 32 + lane)) & (NSP - 1);
        float4 v = *reinterpret_cast<const float4*>(urow + pos);
        Plo[g] = pk(v.x, v.y);
        Phi[g] = pk(v.z, v.w);
    }

    const bool own0 = (lane >= 16);
    const bool own1 = (lane < 16);
    const int  pos0 = ws + 4 * lane;         // valid (in [0,NSP)) when own0
    const int  pos1 = ws + 128 + 4 * lane;   // valid when own1

    // frame 0 = u0
    {
        float* o0 = out + (size_t)row * NSP;
        if (own0) { longlong2 v = make_longlong2((long long)Plo[0], (long long)Phi[0]);
                    __stcs(reinterpret_cast<longlong2*>(o0 + pos0), v); }
        if (own1) { longlong2 v = make_longlong2((long long)Plo[1], (long long)Phi[1]);
                    __stcs(reinterpret_cast<longlong2*>(o0 + pos1), v); }
    }

    const uint32_t shbase = (uint32_t)__cvta_generic_to_shared(sh);
    const uint32_t peer   = (uint32_t)(half ^ 1);

    asm volatile("barrier.cluster.arrive.aligned;" ::: "memory");

    float* ofr = out + (size_t)BATCH * NSP + (size_t)row * NSP;   // frame 1

    #pragma unroll 1
    for (int t = 0; t < NSTEP; t++) {
        if (t > 0 && (t & (KEX - 1)) == 0) {
            // ===== ghost exchange (every KEX steps) =====
            asm volatile("barrier.cluster.wait.aligned;" ::: "memory");

            // publish owned groups into CTA-owned index space [0,1024)
            if (own0) {
                float a, b, c, d; upk(Plo[0], a, b); upk(Phi[0], c, d);
                *reinterpret_cast<float4*>(&sh[pos0 - half * OWN_CTA]) =
                    make_float4(a, b, c, d);
            }
            if (own1) {
                float a, b, c, d; upk(Plo[1], a, b); upk(Phi[1], c, d);
                *reinterpret_cast<float4*>(&sh[pos1 - half * OWN_CTA]) =
                    make_float4(a, b, c, d);
            }
            __syncthreads();
            asm volatile("barrier.cluster.arrive.aligned;" ::: "memory");
            asm volatile("barrier.cluster.wait.aligned;"   ::: "memory");

            // refill ghost groups (m<16 or m>=48) from own sh or peer DSMEM
            #pragma unroll
            for (int g = 0; g < NG; g++) {
                bool ghost = (g == 0) ? (lane < 16) : (lane >= 16);
                if (ghost) {
                    int pos = (ws + 4 * (g * 32 + lane)) & (NSP - 1);
                    int h2  = pos >> 10;
                    int idx = pos & (OWN_CTA - 1);
                    float4 v;
                    if (h2 == half) {
                        v = *reinterpret_cast<const float4*>(&sh[idx]);
                    } else {
                        uint32_t pa;
                        asm("mapa.shared::cluster.u32 %0, %1, %2;"
                            : "=r"(pa) : "r"(shbase + (uint32_t)idx * 4u), "r"(peer));
                        asm volatile("ld.shared::cluster.v4.f32 {%0,%1,%2,%3}, [%4];"
                                     : "=f"(v.x), "=f"(v.y), "=f"(v.z), "=f"(v.w)
                                     : "r"(pa));
                    }
                    Plo[g] = pk(v.x, v.y);
                    Phi[g] = pk(v.z, v.w);
                }
            }
            __syncthreads();
            asm volatile("barrier.cluster.arrive.aligned;" ::: "memory");
        }

        // ===== one step, registers + shuffles only =====
        // neighbor pairs: group m-1's top pair, group m+1's bottom pair
        u64 pH0 = __shfl_up_sync(FULL, Phi[0], 1);            // lane0: ghost edge garbage
        u64 a1  = __shfl_up_sync(FULL, Phi[1], 1);
        u64 b1  = __shfl_sync(FULL, Phi[0], 31);
        u64 pH1 = (lane == 0) ? b1 : a1;
        u64 nL1 = __shfl_down_sync(FULL, Plo[1], 1);          // lane31: ghost edge garbage
        u64 a0  = __shfl_down_sync(FULL, Plo[0], 1);
        u64 b0  = __shfl_sync(FULL, Plo[1], 0);
        u64 nL0 = (lane == 31) ? b0 : a0;

        u64 rlo[NG], rhi[NG];
        #pragma unroll
        for (int g = 0; g < NG; g++) {
            u64 prev = (g == 0) ? pH0 : pH1;
            u64 next = (g == 0) ? nL0 : nL1;
            float p2, p3, e0, e1, e2, e3, n0, n1;
            upk(prev, p2, p3);
            upk(Plo[g], e0, e1);
            upk(Phi[g], e2, e3);
            upk(next, n0, n1);
            u64 O0 = pk(p3, e0);
            u64 O1 = pk(e1, e2);
            u64 O2 = pk(e3, n0);

            // pair (e0,e1): um2=prev, up2=Phi, um1=O0, up1=O1
            {
                u64 s1  = add2(O1, O0);
                u64 s2  = add2(Phi[g], prev);
                u64 d1  = fma2(M1, O0, O1);
                u64 lin = mul2(C0, Plo[g]);
                lin = fma2(C1, s1, lin);
                lin = fma2(C2, s2, lin);
                u64 tn  = mul2(AV, Plo[g]);
                rlo[g] = fma2(tn, d1, lin);
            }
            // pair (e2,e3): um2=Plo, up2=next, um1=O1, up1=O2
            {
                u64 s1  = add2(O2, O1);
                u64 s2  = add2(next, Plo[g]);
                u64 d1  = fma2(M1, O1, O2);
                u64 lin = mul2(C0, Phi[g]);
                lin = fma2(C1, s1, lin);
                lin = fma2(C2, s2, lin);
                u64 tn  = mul2(AV, Phi[g]);
                rhi[g] = fma2(tn, d1, lin);
            }
        }

        // stream trajectory frame (owned groups, contiguous half-warp stores)
        if (own0) { longlong2 v = make_longlong2((long long)rlo[0], (long long)rhi[0]);
                    __stcs(reinterpret_cast<longlong2*>(ofr + pos0), v); }
        if (own1) { longlong2 v = make_longlong2((long long)rlo[1], (long long)rhi[1]);
                    __stcs(reinterpret_cast<longlong2*>(ofr + pos1), v); }

        #pragma unroll
        for (int g = 0; g < NG; g++) { Plo[g] = rlo[g]; Phi[g] = rhi[g]; }
        ofr += (size_t)BATCH * NSP;
    }

    asm volatile("barrier.cluster.wait.aligned;" ::: "memory");
}

extern "C" void kernel_launch(void* const* d_in, const int* in_sizes, int n_in,
                              void* d_out, int out_size) {
    const float* u0    = (const float*)d_in[0];
    const float* c     = (const float*)d_in[1];
    const float* alpha = (const float*)d_in[2];
    const float* beta  = (const float*)d_in[3];
    float* out = (float*)d_out;

    ks_kernel<<<BATCH * 2, THREADS>>>(u0, c, alpha, beta, out);
}